// round 17
// baseline (speedup 1.0000x reference)
#include <cuda_runtime.h>
#include <cuda_fp16.h>
#include <math.h>
#include <stdint.h>

// loss = mean_n [ logsumexp_m( q_n . t_m ) - q_n . t_n ],  q = logits - log(noise)
// N = M = 16384, D = 64.
// Single-term fp16 mma.sync; 4x4 warp grid; fixed-shift Schraudolph softmax
// with MAGIC-ADD exp (FFMA+FMNMX+SHL+FADD, no CVT, no MUFU); 4-deep ring.

#define NTOT    16384
#define DIM     64
#define TM      128
#define TN      128
#define NTILES  (NTOT / TN)         // 128
#define NBLOCKS (NTOT / TM)         // 128
#define NTHREADS 512
#define CSHIFT 50.0f

// Schraudolph: i = round(v*A + B) is the f32 bit pattern of e^(v-C).
// A = 2^23/ln2; B = 127*2^23 - 0.0563*2^23 - C*A (zero-mean error offset).
// Magic-add: r = v*A + (B + 2^31) stays in the [2^31, 2^32) binade for all
// reachable v, so bits(r) = bits(2^31) + round_256(v*A+B)>>8 and since
// bits(2^31)<<8 == 0 (mod 2^32):  e^(v-C) = as_float(bits(r) << 8).
// fmaxf clamp at 2^31 makes underflow exactly 0.0f.
#define SCH_A   12102203.0f
#define SCH_BM  2607254260.0f       // 459770612 + 2^31
#define SCH_MAG 2147483648.0f       // 2^31

__device__ __align__(128) unsigned char g_thf[(size_t)NTOT * 128];
__device__ float g_partial[NBLOCKS];
__device__ unsigned int g_done;

// ---------------- PTX helpers ----------------
static __device__ __forceinline__ uint32_t smem_u32(const void* p) {
    uint32_t a;
    asm("{ .reg .u64 t; cvta.to.shared.u64 t, %1; cvt.u32.u64 %0, t; }"
        : "=r"(a) : "l"(p));
    return a;
}
static __device__ __forceinline__ float schexp(float v) {
    float r = fmaf(v, SCH_A, SCH_BM);
    r = fmaxf(r, SCH_MAG);
    return __uint_as_float(__float_as_uint(r) << 8);
}
#define MBAR_INIT(a, c) \
    asm volatile("mbarrier.init.shared.b64 [%0], %1;" :: "r"(a), "r"(c) : "memory")
#define MBAR_EXPECT(a, b) \
    asm volatile("mbarrier.arrive.expect_tx.shared.b64 _, [%0], %1;" :: "r"(a), "r"(b) : "memory")
#define MBAR_ARRIVE(a) \
    asm volatile("mbarrier.arrive.shared.b64 _, [%0];" :: "r"(a) : "memory")
#define MBAR_WAIT(a, ph) do {                                                        \
    uint32_t _m = (a), _p = (ph), _d;                                                \
    asm volatile("{ .reg .pred p; mbarrier.try_wait.parity.acquire.cta.shared::cta.b64 p, [%1], %2; selp.b32 %0,1,0,p; }" \
                 : "=r"(_d) : "r"(_m), "r"(_p) : "memory");                          \
    if (!_d) {                                                                       \
        asm volatile("{ .reg .pred P1; WL%=: mbarrier.try_wait.parity.acquire.cta.shared::cta.b64 P1, [%0], %1, 0x989680; @P1 bra.uni WD%=; bra.uni WL%=; WD%=: }" \
                     :: "r"(_m), "r"(_p) : "memory");                                \
    }                                                                                \
} while (0)

static __device__ __forceinline__ void bulk_g2s(uint32_t dst, const void* src,
                                                uint32_t bytes, uint32_t mbar) {
    uint64_t g;
    asm("cvta.to.global.u64 %0, %1;" : "=l"(g) : "l"(src));
    asm volatile("cp.async.bulk.shared::cta.global.mbarrier::complete_tx::bytes [%0], [%1], %2, [%3];"
                 :: "r"(dst), "l"(g), "r"(bytes), "r"(mbar) : "memory");
}

#define LDSM4(r, a) \
    asm volatile("ldmatrix.sync.aligned.m8n8.x4.shared.b16 {%0,%1,%2,%3}, [%4];" \
                 : "=r"((r)[0]), "=r"((r)[1]), "=r"((r)[2]), "=r"((r)[3]) : "r"(a))

#define MMA16816(d, a, b0, b1) \
    asm volatile("mma.sync.aligned.m16n8k16.row.col.f32.f16.f16.f32 " \
                 "{%0,%1,%2,%3}, {%4,%5,%6,%7}, {%8,%9}, {%0,%1,%2,%3};" \
                 : "+f"((d)[0]), "+f"((d)[1]), "+f"((d)[2]), "+f"((d)[3]) \
                 : "r"((a)[0]), "r"((a)[1]), "r"((a)[2]), "r"((a)[3]), \
                   "r"(b0), "r"(b1))

#define MMA16816Z(d, a, b0, b1) \
    asm volatile("mma.sync.aligned.m16n8k16.row.col.f32.f16.f16.f32 " \
                 "{%0,%1,%2,%3}, {%4,%5,%6,%7}, {%8,%9}, {%10,%10,%10,%10};" \
                 : "=f"((d)[0]), "=f"((d)[1]), "=f"((d)[2]), "=f"((d)[3]) \
                 : "r"((a)[0]), "r"((a)[1]), "r"((a)[2]), "r"((a)[3]), \
                   "r"(b0), "r"(b1), "f"(0.0f))

static __device__ __forceinline__ uint32_t pack_h2(float a, float b) {
    __half2 h = __floats2half2_rn(a, b);
    return *reinterpret_cast<uint32_t*>(&h);
}

// ---------------- prep ----------------
__global__ void __launch_bounds__(256) prep_targets(const float* __restrict__ tg) {
    int idx = blockIdx.x * 256 + threadIdx.x;
    int row = idx >> 3, c = idx & 7;
    const float4* p = reinterpret_cast<const float4*>(tg + (size_t)row * DIM + c * 8);
    float4 a = p[0], b = p[1];
    uint4 u = make_uint4(pack_h2(a.x, a.y), pack_h2(a.z, a.w),
                         pack_h2(b.x, b.y), pack_h2(b.z, b.w));
    int slot = row * 8 + (c ^ (row & 7));
    reinterpret_cast<uint4*>(g_thf)[slot] = u;
}

// SMEM: [0,16K) q fp16, [16K + s*16K) tile ring s=0..3, [80K) mbarriers
#define QOFF  0u
#define TBUF(s) (16384u + (uint32_t)(s) * 16384u)
#define BARO  81920u
#define SMEM_BYTES (81920 + 128)

__global__ void __launch_bounds__(NTHREADS, 1)
infonce_mma(const float* __restrict__ logits, const float* __restrict__ noise,
            float* __restrict__ out) {
    extern __shared__ unsigned char smem[];
    const uint32_t sb = smem_u32(smem);
    const int tid = threadIdx.x, wid = tid >> 5, lane = tid & 31;
    const int b = blockIdx.x;

    if (tid == 0) {
#pragma unroll
        for (int s = 0; s < 4; s++) {
            MBAR_INIT(sb + BARO + s * 8, 1);
            MBAR_INIT(sb + BARO + 32 + s * 8, 16);
        }
    }

    // ---- q prologue: q = logits - log(noise) -> fp16, swizzled ----
#pragma unroll
    for (int i = 0; i < 2; i++) {
        int ch = tid + NTHREADS * i;
        int row = ch >> 3, c = ch & 7;
        const float4* p = reinterpret_cast<const float4*>(
            logits + (size_t)(b * TM + row) * DIM + c * 8);
        float4 a = p[0], bb = p[1];
        float x[8] = {a.x, a.y, a.z, a.w, bb.x, bb.y, bb.z, bb.w};
#pragma unroll
        for (int j = 0; j < 8; j++) x[j] -= logf(noise[c * 8 + j]);
        uint4 u = make_uint4(pack_h2(x[0], x[1]), pack_h2(x[2], x[3]),
                             pack_h2(x[4], x[5]), pack_h2(x[6], x[7]));
        uint32_t off = (uint32_t)row * 128u + (uint32_t)((c ^ (row & 7)) * 16);
        *reinterpret_cast<uint4*>(smem + QOFF + off) = u;
    }

    if (tid == 0) {
#pragma unroll
        for (int s = 0; s < 4; s++) {
            MBAR_EXPECT(sb + BARO + s * 8, 16384);
            bulk_g2s(sb + TBUF(s), g_thf + (size_t)s * 16384, 16384, sb + BARO + s * 8);
        }
    }
    __syncthreads();

    // warp grid: 4 x 4; warp tile = 32 rows x 32 cols
    const int wr = wid & 3, wc = wid >> 2;
    const int lrow  = lane & 15;
    const int lchk  = lane >> 4;
    const int swrow = lane & 7;

    uint32_t swk[4];
#pragma unroll
    for (int k = 0; k < 4; k++)
        swk[k] = (uint32_t)(((k * 2 + lchk) ^ swrow) << 4);

    uint32_t A[2][4][4];
#pragma unroll
    for (int mt = 0; mt < 2; mt++) {
        const uint32_t a_base = sb + QOFF +
            (uint32_t)(wr * 32 + mt * 16 + lrow) * 128u;
#pragma unroll
        for (int k = 0; k < 4; k++)
            LDSM4(A[mt][k], a_base + swk[k]);
    }

    uint32_t tbs[4];
#pragma unroll
    for (int s = 0; s < 4; s++)
        tbs[s] = sb + TBUF(s) + (uint32_t)(wc * 32 + lrow) * 128u;

    float ss[4], diagv[4];
#pragma unroll
    for (int j = 0; j < 4; j++) { ss[j] = 0.0f; diagv[j] = 0.0f; }

    for (int t = 0; t < NTILES; t++) {
        const int s = t & 3;
        const int ph = (t >> 2) & 1;
        MBAR_WAIT(sb + BARO + s * 8, ph);

        float acc[8][4];
        const uint32_t th_base = tbs[s];

#pragma unroll
        for (int k = 0; k < 4; k++) {
            uint32_t B[2][4];
            LDSM4(B[0], th_base + swk[k]);
            LDSM4(B[1], th_base + 2048u + swk[k]);
            if (k == 0) {
#pragma unroll
                for (int mt = 0; mt < 2; mt++)
#pragma unroll
                    for (int nt = 0; nt < 4; nt++) {
                        const int g = nt >> 1, su = nt & 1;
                        MMA16816Z(acc[mt * 4 + nt], A[mt][0], B[g][su], B[g][2 + su]);
                    }
            } else {
#pragma unroll
                for (int mt = 0; mt < 2; mt++)
#pragma unroll
                    for (int nt = 0; nt < 4; nt++) {
                        const int g = nt >> 1, su = nt & 1;
                        MMA16816(acc[mt * 4 + nt], A[mt][k], B[g][su], B[g][2 + su]);
                    }
            }
        }

        if (lane == 0) MBAR_ARRIVE(sb + BARO + 32 + s * 8);

        // ---- diagonal extraction (tile t == blockIdx.x) ----
        if (t == b) {
#pragma unroll
            for (int j = 0; j < 4; j++) {
                const int mt = j >> 1, e = j & 1;
                const int rloc = wr * 32 + mt * 16 + e * 8 + (lane >> 2);
                const int cw = rloc - wc * 32;
                if (cw >= 0 && cw < 32) {
                    const int nt = cw >> 3;
                    if (((cw >> 1) & 3) == (lane & 3))
                        diagv[j] = acc[mt * 4 + nt][e * 2 + (cw & 1)];
                }
            }
        }

        // ---- fixed-shift magic-add softmax accumulation (no CVT/MUFU) ----
#pragma unroll
        for (int j = 0; j < 4; j++) {
            const int mt = j >> 1, er = (j & 1) * 2;
            float s0 = 0.f, s1 = 0.f;
#pragma unroll
            for (int nt = 0; nt < 4; nt++) {
                s0 += schexp(acc[mt * 4 + nt][er]);
                s1 += schexp(acc[mt * 4 + nt][er + 1]);
            }
            ss[j] += s0 + s1;
        }

        if (t + 4 < NTILES && tid == 0) {
            MBAR_WAIT(sb + BARO + 32 + s * 8, ph);
            MBAR_EXPECT(sb + BARO + s * 8, 16384);
            bulk_g2s(sb + TBUF(s), g_thf + (size_t)(t + 4) * 16384, 16384,
                     sb + BARO + s * 8);
        }
    }

    // ---- quad merges (sum + diag), then block reduce over 4 col-groups ----
    __syncthreads();
    float* S = reinterpret_cast<float*>(smem);

#pragma unroll
    for (int j = 0; j < 4; j++) {
        float v = ss[j];
        v += __shfl_xor_sync(0xffffffffu, v, 1);
        v += __shfl_xor_sync(0xffffffffu, v, 2);
        ss[j] = v;
        float d = diagv[j];
        d += __shfl_xor_sync(0xffffffffu, d, 1);
        d += __shfl_xor_sync(0xffffffffu, d, 2);
        diagv[j] = d;
    }
    if ((lane & 3) == 0) {
#pragma unroll
        for (int j = 0; j < 4; j++) {
            const int mt = j >> 1, e = j & 1;
            const int r = wr * 32 + mt * 16 + e * 8 + (lane >> 2);
            S[wc * 128 + r]       = ss[j];
            S[512 + wc * 128 + r] = diagv[j];
        }
    }
    __syncthreads();

    float loss = 0.0f;
    if (tid < 128) {
        float ssum = 0.0f, d = 0.0f;
#pragma unroll
        for (int g = 0; g < 4; g++) {
            ssum += S[g * 128 + tid];
            d    += S[512 + g * 128 + tid];
        }
        loss = CSHIFT + logf(ssum) - d;
    }
#pragma unroll
    for (int o = 16; o > 0; o >>= 1)
        loss += __shfl_xor_sync(0xffffffffu, loss, o);
    __syncthreads();
    if (lane == 0) S[1024 + wid] = loss;
    __syncthreads();

    // ---- fused finalize ----
    __shared__ unsigned int ticket;
    if (tid == 0) {
        float v = 0.0f;
#pragma unroll
        for (int i = 0; i < 16; i++) v += S[1024 + i];
        g_partial[b] = v;
        __threadfence();
        ticket = atomicAdd(&g_done, 1u);
    }
    __syncthreads();
    if (ticket == NBLOCKS - 1) {
        __threadfence();
        float v = (tid < NBLOCKS) ? g_partial[tid] : 0.0f;
#pragma unroll
        for (int o = 16; o > 0; o >>= 1)
            v += __shfl_xor_sync(0xffffffffu, v, o);
        if (lane == 0) S[1056 + wid] = v;
        __syncthreads();
        if (tid == 0) {
            float r = 0.0f;
#pragma unroll
            for (int i = 0; i < 16; i++) r += S[1056 + i];
            out[0] = r / (float)NTOT;
            g_done = 0;
        }
    }
}

extern "C" void kernel_launch(void* const* d_in, const int* in_sizes, int n_in,
                              void* d_out, int out_size) {
    const float* logits  = (const float*)d_in[0];
    const float* targets = (const float*)d_in[1];
    const float* noise   = (const float*)d_in[2];

    cudaFuncSetAttribute(infonce_mma, cudaFuncAttributeMaxDynamicSharedMemorySize, SMEM_BYTES);

    prep_targets<<<NTOT * 8 / 256, 256>>>(targets);
    infonce_mma<<<NBLOCKS, NTHREADS, SMEM_BYTES>>>(logits, noise, (float*)d_out);
}